// round 15
// baseline (speedup 1.0000x reference)
#include <cuda_runtime.h>
#include <math.h>

#define BB 2
#define SS 4096
#define DM 768
#define HH 12
#define OUTN 512
#define GRID 128
#define NTHR 512
#define ROWS_PB 64
#define STROWS 16
#define NST 4
#define XSTR 772
#define XBUFF 12352

// smem float offsets (stage 2)
#define OFF_U    0           // u_s [m][h] : 9216
#define OFF_X    9216        // 3 x-buffers : 37056
#define OFF_E    46272       // e_s : 192
#define SMEM_FLOATS 46464    // 185856 B

// ---------------- scratch (all slot-complete; NO init ordering needed) ------
__device__ float g_qg[BB*DM];
__device__ float g_u[BB*DM*HH];          // [b][m][h]
__device__ float g_y[GRID*HH*DM];        // stage-2 slot per block
__device__ float g_dpart[GRID*HH];       // stage-2 denom partial per block
__device__ float g_ogp[8*DM];            // stage-3 og partials [sub*2+b][o]
__device__ float g_p1[8*DM];             // stage-4 partials [mp*2+b][o]
__device__ float g_p2[8*DM];             // stage-5 partials [mp*2+b][o]
__device__ unsigned g_cnt;               // monotonic grid-barrier counter

typedef unsigned long long ull;

// ---------------- f32x2 helpers ---------------------------------------------
#define FMA2(d,a,b,c) asm("fma.rn.f32x2 %0, %1, %2, %3;" : "=l"(d) : "l"(a), "l"(b), "l"(c))
#define ADD2(d,a,b)   asm("add.rn.f32x2 %0, %1, %2;" : "=l"(d) : "l"(a), "l"(b))
#define PACK2(d,lo,hi) asm("mov.b64 %0, {%1,%2};" : "=l"(d) : "f"(lo), "f"(hi))
#define UNPK2(lo,hi,s) asm("mov.b64 {%0,%1}, %2;" : "=f"(lo), "=f"(hi) : "l"(s))

// ---------------- fence-free grid barrier (release/acquire; replay-safe) ----
__device__ __forceinline__ void gbar() {
    __syncthreads();
    if (threadIdx.x == 0) {
        unsigned arr;
        asm volatile("atom.release.gpu.global.add.u32 %0, [%1], 1;"
                     : "=r"(arr) : "l"(&g_cnt) : "memory");
        unsigned target = (arr / GRID + 1u) * GRID;
        unsigned cur;
        do {
            asm volatile("ld.acquire.gpu.global.u32 %0, [%1];"
                         : "=r"(cur) : "l"(&g_cnt) : "memory");
        } while (cur < target);
    }
    __syncthreads();
}

__global__ __launch_bounds__(NTHR, 1)
void k_mega(const float* __restrict__ x,   const float* __restrict__ wqg,
            const float* __restrict__ bqg, const float* __restrict__ wkg,
            const float* __restrict__ wvg, const float* __restrict__ bvg,
            const float* __restrict__ wo,  const float* __restrict__ bo,
            const float* __restrict__ wp,  const float* __restrict__ bp,
            const float* __restrict__ wfc, const float* __restrict__ bfc,
            float* __restrict__ out) {
    extern __shared__ __align__(16) float sm[];
    const int blk = blockIdx.x;
    const int t = threadIdx.x;

    // ======== S0: qg (24 blocks) + out=bfc (block 24) =======================
    if (blk < 24) {
        int b = blk / 12, h = blk % 12;
        float* x0s = sm; float* redA = sm + 768;
        for (int i = t; i < DM; i += NTHR) x0s[i] = x[(size_t)b*SS*DM + i];
        __syncthreads();
        int o = t & 63, part = t >> 6;                 // 8 parts of 96 m
        float acc = 0.f;
        const float* wc = wqg + h*64 + o;
        #pragma unroll 16
        for (int j = 0; j < 96; j++) {
            int m = part*96 + j;
            acc += x0s[m] * wc[(size_t)m*DM];
        }
        redA[t] = acc;
        __syncthreads();
        if (t < 64) {
            float s = bqg[h*64 + t];
            #pragma unroll
            for (int k = 0; k < 8; k++) s += redA[k*64 + t];
            g_qg[b*DM + h*64 + t] = s * 0.125f;
        }
    } else if (blk == 24) {
        out[t]       = bfc[t];
        out[512 + t] = bfc[t];
    }
    gbar();

    // ======== S1: u[b,m,h] = qg[b,h,:]·wkg[m,h*64:] (128 blocks) ============
    {
        int b = blk >> 6, mc = blk & 63;
        float* qgs = sm;
        for (int i = t; i < DM; i += NTHR) qgs[i] = g_qg[b*DM + i];
        __syncthreads();
        if (t < 144) {
            int mi = t / 12, h = t % 12;
            int m = mc*12 + mi;
            const float* w = wkg + (size_t)m*DM + h*64;
            const float* q = qgs + h*64;
            float acc = 0.f;
            #pragma unroll
            for (int d = 0; d < 64; d++) acc += q[d] * w[d];
            g_u[((size_t)m + (size_t)b*DM)*HH + h] = acc;   // [b][m][h]
        }
    }
    gbar();

    // ======== S2: cp.async-pipelined scores -> exp -> weighted sums =========
    {
        const int b = blk >> 6;
        const int row0 = (blk & 63) * ROWS_PB;
        float* u_s = sm + OFF_U;
        float* e_s = sm + OFF_E;

        auto issue = [&](int st) {
            if (st < NST) {
                const float* gsrc = x + ((size_t)b*SS + row0 + st*STROWS)*DM;
                float* buf = sm + OFF_X + (st % 3)*XBUFF;
                #pragma unroll
                for (int k = 0; k < 6; k++) {
                    int idx4 = t + k*NTHR;
                    int row = idx4 / 192, c4 = idx4 % 192;
                    unsigned smaddr = (unsigned)__cvta_generic_to_shared(
                        buf + row*XSTR + c4*4);
                    const float4* g = (const float4*)(gsrc + (size_t)row*DM) + c4;
                    asm volatile("cp.async.cg.shared.global [%0], [%1], 16;"
                                 :: "r"(smaddr), "l"(g) : "memory");
                }
            }
            asm volatile("cp.async.commit_group;" ::: "memory");
        };

        issue(0);
        issue(1);

        {
            const float4* src = (const float4*)(g_u + (size_t)b*DM*HH);
            float4* dst = (float4*)u_s;
            for (int i = t; i < DM*HH/4; i += NTHR) dst[i] = src[i];
        }

        const int hh = t >> 8, tc = t & 255;
        ull acc[3][3];
        #pragma unroll
        for (int c = 0; c < 3; c++)
            #pragma unroll
            for (int k = 0; k < 3; k++) acc[c][k] = 0ull;
        float dloc = 0.f;

        #pragma unroll
        for (int st = 0; st < NST; st++) {
            issue(st + 2);
            asm volatile("cp.async.wait_group 2;" ::: "memory");
            __syncthreads();

            const float* xb = sm + OFF_X + (st % 3)*XBUFF;

            // ---- phase 1: warp-m-split scores. warp w owns m in [48w,48w+48)
            {
                int w = t >> 5, l = t & 31;
                int row = l >> 1, mh = l & 1;
                int m0 = w*48 + mh*24;
                const float4* xr = (const float4*)(xb + row*XSTR + m0);
                const float* up = u_s + m0*HH;
                ull a2[6];
                #pragma unroll
                for (int k = 0; k < 6; k++) a2[k] = 0ull;
                #pragma unroll
                for (int i = 0; i < 6; i++) {
                    float4 xv = xr[i];
                    #pragma unroll
                    for (int j = 0; j < 4; j++) {
                        float xs = (j==0) ? xv.x : (j==1) ? xv.y
                                 : (j==2) ? xv.z : xv.w;
                        ull xx;
                        PACK2(xx, xs, xs);
                        const ulonglong2* uu =
                            (const ulonglong2*)(up + (i*4 + j)*HH);
                        ulonglong2 u0 = uu[0], u1 = uu[1], u2 = uu[2];
                        FMA2(a2[0], xx, u0.x, a2[0]);
                        FMA2(a2[1], xx, u0.y, a2[1]);
                        FMA2(a2[2], xx, u1.x, a2[2]);
                        FMA2(a2[3], xx, u1.y, a2[3]);
                        FMA2(a2[4], xx, u2.x, a2[4]);
                        FMA2(a2[5], xx, u2.y, a2[5]);
                    }
                }
                #pragma unroll
                for (int k = 0; k < 6; k++) {
                    ull o2 = __shfl_xor_sync(0xffffffffu, a2[k], 1);
                    ADD2(a2[k], a2[k], o2);
                }
                if (mh == 0) {
                    float v[12];
                    #pragma unroll
                    for (int k = 0; k < 6; k++) UNPK2(v[2*k], v[2*k+1], a2[k]);
                    // cross-warp m-reduction via smem scratch in x buffer gap
                    // use e_s staging: scr rows at sm+OFF_E+... (reuse u tail)
                    #pragma unroll
                    for (int h = 0; h < 12; h++)
                        atomicAdd(&e_s[row*HH + h], 0.f), (void)0;   // placeholder never taken
                }
                // store partials: scr region = first 16*12*16 floats of buf (st+3)%3 is unsafe;
                // use dedicated scr in u_s tail? u_s fully used. Use shuffle tree instead:
                // reduce across the 16 warps via smem at e_s+192 is out of range.
                // -> we do a second-level reduction through global-free smem: reuse
                //    the 192-float e_s with 16-way atomic-free striped writes below.
                (void)0;
            }
            // --- cross-warp reduction done with a small dedicated scratch ----
            {
                // scr lives in the THIRD x-buffer only when it is not in flight:
                // with depth 2 (wait_group 2 above), buffer (st+2)%3 is being filled,
                // buffers st%3 (current) and (st+1)%3 (next) hold data. None free.
                // Instead: warp-level partials were already pair-summed; finish with
                // shared atomics on e_s (12 floats per row, 16 warps): zero first.
            }
            __syncthreads();
            if (t < STROWS*HH) e_s[t] = 0.f;
            __syncthreads();
            {
                int w = t >> 5, l = t & 31;
                int row = l >> 1, mh = l & 1;
                if (mh == 0) {
                    // recompute v from a2 is lost; so instead accumulate via shared atomics here
                }
            }
            // NOTE: simplified correct path below recomputes phase 1 with the
            // original conflict-free 8-lane layout (known-good from R5/R8).
            {
                int rw = t >> 4, p = t & 15;          // 32 rows? STROWS=16 -> rw<32 invalid
            }
            __syncthreads();

            // ---- phase 1 (authoritative, known-good): 16 rows x 32 lanes
            {
                int rw = t >> 5, p = t & 31;          // 16 rows, 32 lanes each
                const float* xr = xb + rw*XSTR;
                ull aA[6];
                #pragma unroll
                for (int k = 0; k < 6; k++) aA[k] = 0ull;
                #pragma unroll 8
                for (int i = 0; i < 24; i++) {
                    int m = i*32 + p;
                    float xv = xr[m];
                    ull xx;
                    PACK2(xx, xv, xv);
                    const ulonglong2* u2p = (const ulonglong2*)(u_s + m*HH);
                    ulonglong2 w0 = u2p[0], w1 = u2p[1], w2 = u2p[2];
                    FMA2(aA[0], xx, w0.x, aA[0]); FMA2(aA[1], xx, w0.y, aA[1]);
                    FMA2(aA[2], xx, w1.x, aA[2]); FMA2(aA[3], xx, w1.y, aA[3]);
                    FMA2(aA[4], xx, w2.x, aA[4]); FMA2(aA[5], xx, w2.y, aA[5]);
                }
                #pragma unroll
                for (int off = 16; off; off >>= 1)
                    #pragma unroll
                    for (int k = 0; k < 6; k++) {
                        ull o2 = __shfl_xor_sync(0xffffffffu, aA[k], off);
                        ADD2(aA[k], aA[k], o2);
                    }
                if (p == 0) {
                    float v[12];
                    #pragma unroll
                    for (int k = 0; k < 6; k++) UNPK2(v[2*k], v[2*k+1], aA[k]);
                    #pragma unroll
                    for (int h = 0; h < 12; h++)
                        e_s[rw*HH + h] = __expf(v[h]);
                }
            }
            __syncthreads();

            if (t < HH) {
                #pragma unroll
                for (int j = 0; j < STROWS; j++) dloc += e_s[j*HH + t];
            }

            // ---- phase 2: y[h][m] += sum_s e[s][h]*x[s][m]
            {
                #pragma unroll 4
                for (int s = 0; s < STROWS; s++) {
                    float xv0 = xb[s*XSTR + tc];
                    float xv1 = xb[s*XSTR + 256 + tc];
                    float xv2 = xb[s*XSTR + 512 + tc];
                    ull xx0, xx1, xx2;
                    PACK2(xx0, xv0, xv0);
                    PACK2(xx1, xv1, xv1);
                    PACK2(xx2, xv2, xv2);
                    const ull* ep = (const ull*)(e_s + s*HH + hh*6);
                    ull e0 = ep[0], e1 = ep[1], e2 = ep[2];
                    FMA2(acc[0][0], e0, xx0, acc[0][0]);
                    FMA2(acc[0][1], e1, xx0, acc[0][1]);
                    FMA2(acc[0][2], e2, xx0, acc[0][2]);
                    FMA2(acc[1][0], e0, xx1, acc[1][0]);
                    FMA2(acc[1][1], e1, xx1, acc[1][1]);
                    FMA2(acc[1][2], e2, xx1, acc[1][2]);
                    FMA2(acc[2][0], e0, xx2, acc[2][0]);
                    FMA2(acc[2][1], e1, xx2, acc[2][1]);
                    FMA2(acc[2][2], e2, xx2, acc[2][2]);
                }
            }
            __syncthreads();
        }
        asm volatile("cp.async.wait_group 0;" ::: "memory");

        // ---- write this block's y slot + denom partial (no atomics)
        {
            size_t base = (size_t)blk*HH + hh*6;
            #pragma unroll
            for (int c = 0; c < 3; c++)
                #pragma unroll
                for (int k = 0; k < 3; k++) {
                    float f0, f1;
                    UNPK2(f0, f1, acc[c][k]);
                    g_y[(base + 2*k  )*DM + c*256 + tc] = f0;
                    g_y[(base + 2*k+1)*DM + c*256 + tc] = f1;
                }
        }
        if (t < HH) g_dpart[blk*HH + t] = dloc;
    }
    gbar();

    // ======== S3: og partials = (y/denom) @ wvg slice (96 blocks, no atomics)
    if (blk < 96) {
        int b = blk / 48; int r = blk % 48;
        int h = r >> 2; int sub = r & 3;                 // 4 subs of 192 m
        float* redR = sm;            // 384
        float* y_s  = sm + 384;      // 192
        float* redG = sm + 768;      // 512
        float* redD = sm + 1280;     // 64 + 1
        if (t < 64) redD[t] = g_dpart[(b*64 + t)*HH + h];
        __syncthreads();
        if (t == 0) {
            float s = 0.f;
            #pragma unroll
            for (int k = 0; k < 64; k++) s += redD[k];
            redD[64] = 1.f / s;
        }
        if (t < 384) {
            int e = t % 192, prt = t / 192;
            float s = 0.f;
            #pragma unroll 8
            for (int sl = b*64 + prt*32; sl < b*64 + prt*32 + 32; sl++)
                s += g_y[((size_t)sl*HH + h)*DM + sub*192 + e];
            redR[t] = s;
        }
        __syncthreads();
        float inv = redD[64];
        if (t < 192) y_s[t] = (redR[t] + redR[192+t]) * inv;
        __syncthreads();
        int o = t & 63, q = t >> 6;          // 8 parts of 24 m
        float acc = 0.f;
        const float* wc = wvg + h*64 + o;
        #pragma unroll
        for (int j = 0; j < 24; j++) {
            int ml = q*24 + j;
            acc += y_s[ml] * wc[(size_t)(sub*192 + ml)*DM];
        }
        redG[t] = acc;
        __syncthreads();
        if (t < 64) {
            float s = 0.f;
            #pragma unroll
            for (int k = 0; k < 8; k++) s += redG[k*64 + t];
            g_ogp[(sub*2 + b)*DM + h*64 + t] = s;        // complete slot
        }
    }
    gbar();

    // ======== S4: attn0 partials: og @ wo (24 blocks, slot writes) ==========
    if (blk < 24) {
        int b = blk / 12; int r = blk % 12;
        int oc = r / 4;   int mp = r % 4;
        float* in_s = sm; float* redG = sm + 192;
        if (t < 192) {
            int m = mp*192 + t;
            in_s[t] = bvg[m] + g_ogp[(0*2+b)*DM + m] + g_ogp[(1*2+b)*DM + m]
                             + g_ogp[(2*2+b)*DM + m] + g_ogp[(3*2+b)*DM + m];
        }
        __syncthreads();
        int o = oc*256 + (t & 255), mh = t >> 8;
        float acc = 0.f;
        const float* wc = wo + o;
        #pragma unroll 16
        for (int j = 0; j < 96; j++) {
            int m = mp*192 + mh*96 + j;
            acc += in_s[mh*96 + j] * wc[(size_t)m*DM];
        }
        redG[t] = acc;
        __syncthreads();
        if (t < 256)
            g_p1[(mp*2 + b)*DM + oc*256 + t] = redG[t] + redG[256 + t];
    }
    gbar();

    // ======== S5: pooled-pre partials: attn0 @ wp (24 blocks) ===============
    if (blk < 24) {
        int b = blk / 12; int r = blk % 12;
        int oc = r / 4;   int mp = r % 4;
        float* in_s = sm; float* redG = sm + 192;
        if (t < 192) {
            int m = mp*192 + t;
            in_s[t] = bo[m] + g_p1[(0*2+b)*DM + m] + g_p1[(1*2+b)*DM + m]
                            + g_p1[(2*2+b)*DM + m] + g_p1[(3*2+b)*DM + m];
        }
        __syncthreads();
        int o = oc*256 + (t & 255), mh = t >> 8;
        float acc = 0.f;
        const float* wc = wp + o;
        #pragma unroll 16
        for (int j = 0; j < 96; j++) {
            int m = mp*192 + mh*96 + j;
            acc += in_s[mh*96 + j] * wc[(size_t)m*DM];
        }
        redG[t] = acc;
        __syncthreads();
        if (t < 256)
            g_p2[(mp*2 + b)*DM + oc*256 + t] = redG[t] + redG[256 + t];
    }
    gbar();

    // ======== S6: out += tanh(part2) @ wfc (16 blocks, atomic on out) =======
    if (blk < 16) {
        int b = blk / 8; int r = blk % 8;
        int oc = r / 4;  int mp = r % 4;
        float* in_s = sm; float* redG = sm + 192;
        if (t < 192) {
            int m = mp*192 + t;
            float v = bp[m] + g_p2[(0*2+b)*DM + m] + g_p2[(1*2+b)*DM + m]
                            + g_p2[(2*2+b)*DM + m] + g_p2[(3*2+b)*DM + m];
            in_s[t] = tanhf(v);
        }
        __syncthreads();
        int o = oc*256 + (t & 255), mh = t >> 8;
        float acc = 0.f;
        const float* wc = wfc + o;
        #pragma unroll 16
        for (int j = 0; j < 96; j++) {
            int m = mp*192 + mh*96 + j;
            acc += in_s[mh*96 + j] * wc[(size_t)m*OUTN];
        }
        redG[t] = acc;
        __syncthreads();
        if (t < 256)
            atomicAdd(&out[b*OUTN + oc*256 + t], redG[t] + redG[256 + t]);
    }
}

// ---------------- launch ----------------------------------------------------
extern "C" void kernel_launch(void* const* d_in, const int* in_sizes, int n_in,
                              void* d_out, int out_size) {
    const float* x   = (const float*)d_in[0];
    const float* wqg = (const float*)d_in[7];
    const float* bqg = (const float*)d_in[8];
    const float* wkg = (const float*)d_in[9];
    const float* wvg = (const float*)d_in[11];
    const float* bvg = (const float*)d_in[12];
    const float* wo  = (const float*)d_in[13];
    const float* bo  = (const float*)d_in[14];
    const float* wp  = (const float*)d_in[15];
    const float* bp  = (const float*)d_in[16];
    const float* wfc = (const float*)d_in[17];
    const float* bfc = (const float*)d_in[18];
    float* out = (float*)d_out;

    const size_t smem = (size_t)SMEM_FLOATS * sizeof(float);
    static int configured = 0;
    if (!configured) {
        cudaFuncSetAttribute(k_mega, cudaFuncAttributeMaxDynamicSharedMemorySize,
                             (int)smem);
        configured = 1;
    }
    k_mega<<<GRID, NTHR, smem>>>(x, wqg, bqg, wkg, wvg, bvg, wo, bo, wp, bp,
                                 wfc, bfc, out);
}